// round 5
// baseline (speedup 1.0000x reference)
#include <cuda_runtime.h>
#include <math.h>

// ---------------- problem constants ----------------
#define SEQ   10
#define WAY   5
#define SHOT  5
#define TT    45          // C(10,2)
#define D     2048        // OUT_DIM == IN_DIM
#define NQ    75
#define NS    25
#define NQT   3375        // NQ*TT
#define NST   1125        // NS*TT
#define QF    750         // NQ*SEQ query frames
#define SF    250         // NS*SEQ support frames
#define NF    1000        // total frames

// itertools.combinations(range(10), 2) order
__constant__ int c_p0[TT] = {0,0,0,0,0,0,0,0,0, 1,1,1,1,1,1,1,1, 2,2,2,2,2,2,2,
                             3,3,3,3,3,3, 4,4,4,4,4, 5,5,5,5, 6,6,6, 7,7, 8};
__constant__ int c_p1[TT] = {1,2,3,4,5,6,7,8,9, 2,3,4,5,6,7,8,9, 3,4,5,6,7,8,9,
                             4,5,6,7,8,9, 5,6,7,8,9, 6,7,8,9, 7,8,9, 8,9, 9};

// ---------------- scratch (static device memory; no runtime allocs) ----------------
__device__ float g_EF[NF * 2 * D];    // per-frame projections
__device__ float g_QE[NQT * D];       // q_embed
__device__ float g_SE[NST * D];       // support_all flattened [c*225 + s*45 + t]
__device__ float g_qn[NQT];           // squared norms
__device__ float g_sn[NST];
__device__ float g_DQ[NQT * NST];     // cdist(q_embed, support_all)
__device__ float g_SD[NST * NST];     // cdist(support_all, support_all)
__device__ float g_rowmax[WAY * NQT];
__device__ int   g_pos[WAY * NQT];
__device__ float g_ave[WAY * NQT];
__device__ int   g_record[WAY * NST];
__device__ float g_mask[WAY * NST];
__device__ float g_msum[WAY];
__device__ float g_contrast[NQ * WAY];

typedef unsigned long long u64;
typedef unsigned int u32;

__device__ __forceinline__ u64 pk(float lo, float hi) {
    u64 r; asm("mov.b64 %0, {%1, %2};" : "=l"(r) : "f"(lo), "f"(hi)); return r;
}
__device__ __forceinline__ void ffma2(u64& d, u64 a, u64 b) {
    asm("fma.rn.f32x2 %0, %1, %2, %0;" : "+l"(d) : "l"(a), "l"(b));
}
__device__ __forceinline__ float2 upk(u64 v) {
    float2 f; asm("mov.b64 {%0, %1}, %2;" : "=f"(f.x), "=f"(f.y) : "l"(v)); return f;
}

// ---------------- init ----------------
__global__ void k_init() {
    int i = blockIdx.x * blockDim.x + threadIdx.x;
    if (i < WAY * NST) g_record[i] = 0;
    if (i < NQ * WAY)  g_contrast[i] = 0.f;
}

// ---------------- NT SGEMM, FFMA2 core, M-paired accumulators, dup-B smem ----------
// MODE 1: merged distance GEMMs. blockIdx.y<27 -> DQ rows (A=g_QE), else SD rows (A=g_SE).
//         B = g_SE. Epilogue C = sqrt(max(an[r]+bn[c]-2*acc, 0)).
// MODE 2: embedding GEMM: A rows 0..749 queries, 750.. support;
//         B row n -> W + (n&2047)*4096 + (n&2048); plain store to C.
// Thread (tx=tid&15, ty=tid>>4): rows ty*8..ty*8+7 (4 M-pairs), cols tx*NCOL..+NCOL-1.
#define BM 128
#define BK 16
#define AS 136            // A smem row stride (floats): 544B ≡ 32 (mod 128) stagger, 16B aligned

template<int MODE, int BNP, int NCOL>
__global__ void __launch_bounds__(256, 2) sgemm_nt(
    const float* __restrict__ Aq, const float* __restrict__ As_,
    const float* __restrict__ B, float* __restrict__ Cg,
    int M, int N, int ldc)
{
    const int BS2 = 2 * BNP + 8;      // dup-B row stride (floats)
    __shared__ float Ash[BK][AS];
    __shared__ float Bsh[BK][2 * BNP + 8];
    int tid = threadIdx.x;
    int tx = tid & 15, ty = tid >> 4;

    int n0 = blockIdx.x * BNP;
    int m0;
    const float* anp = nullptr; const float* bnp = nullptr;
    float* C = Cg;
    int Mloc = M;
    if (MODE == 1) {
        int y = blockIdx.y;
        if (y < 27) { m0 = y * BM;        anp = g_qn; C = g_DQ; Mloc = NQT; }
        else        { m0 = (y - 27) * BM; anp = g_sn; C = g_SD; Mloc = NST; }
        bnp = g_sn;
    } else {
        m0 = blockIdx.y * BM;
    }

    // ---- loader descriptors ----
    // A: BM*BK/4 = 512 float4 slots, 2 per thread
    const float* aptr[2]; int arow[2], ak4[2];
#pragma unroll
    for (int i = 0; i < 2; i++) {
        int e = tid + i * 256;
        int row = e >> 2; int k4 = (e & 3) * 4;
        arow[i] = row; ak4[i] = k4;
        int r = m0 + row;
        int rc = (r < Mloc) ? r : 0;
        if (MODE == 2) aptr[i] = (rc < QF) ? (Aq + (size_t)rc * D + k4)
                                           : (As_ + (size_t)(rc - QF) * D + k4);
        else {
            const float* Abase = (blockIdx.y < 27) ? g_QE : g_SE;
            aptr[i] = Abase + (size_t)rc * D + k4;
        }
    }
    // B: BNP*BK/4 float4 slots (576 for BNP=144, 512 for 128), up to 3 per thread
    const int BSLOT = BNP * BK / 4;
    const float* bptr[3]; int bcol[3], bk4[3]; bool bok[3];
#pragma unroll
    for (int i = 0; i < 3; i++) {
        int e = tid + i * 256;
        bok[i] = (e < BSLOT);
        int ee = bok[i] ? e : 0;
        int col = ee >> 2; int k4 = (ee & 3) * 4;
        bcol[i] = col; bk4[i] = k4;
        int nr = n0 + col;
        int nc = (nr < N) ? nr : 0;
        if (MODE == 2) bptr[i] = B + (size_t)(nc & 2047) * 4096 + (nc & 2048) + k4;
        else           bptr[i] = g_SE + (size_t)nc * D + k4;
    }

    u64 acc2[4][NCOL];
#pragma unroll
    for (int i = 0; i < 4; i++)
#pragma unroll
        for (int j = 0; j < NCOL; j++) acc2[i][j] = 0ull;

    for (int kk = 0; kk < D; kk += BK) {
        __syncthreads();
        // A tile
#pragma unroll
        for (int i = 0; i < 2; i++) {
            float4 va = *(const float4*)(aptr[i] + kk);
            int row = arow[i], k4 = ak4[i];
            Ash[k4 + 0][row] = va.x; Ash[k4 + 1][row] = va.y;
            Ash[k4 + 2][row] = va.z; Ash[k4 + 3][row] = va.w;
        }
        // B tile (duplicated store)
#pragma unroll
        for (int i = 0; i < 3; i++) {
            if (!bok[i]) break;
            float4 vb = *(const float4*)(bptr[i] + kk);
            int col2 = 2 * bcol[i], k4 = bk4[i];
            *(u64*)&Bsh[k4 + 0][col2] = pk(vb.x, vb.x);
            *(u64*)&Bsh[k4 + 1][col2] = pk(vb.y, vb.y);
            *(u64*)&Bsh[k4 + 2][col2] = pk(vb.z, vb.z);
            *(u64*)&Bsh[k4 + 3][col2] = pk(vb.w, vb.w);
        }
        __syncthreads();
#pragma unroll
        for (int k = 0; k < BK; k++) {
            float4 f0 = *(const float4*)&Ash[k][ty * 8];
            float4 f1 = *(const float4*)&Ash[k][ty * 8 + 4];
            u64 a[4];
            a[0] = pk(f0.x, f0.y); a[1] = pk(f0.z, f0.w);
            a[2] = pk(f1.x, f1.y); a[3] = pk(f1.z, f1.w);
            const u64* bp = (const u64*)&Bsh[k][2 * tx * NCOL];
#pragma unroll
            for (int j = 0; j < NCOL; j++) {
                u64 b = bp[j];
#pragma unroll
                for (int i = 0; i < 4; i++) ffma2(acc2[i][j], a[i], b);
            }
        }
    }

#pragma unroll
    for (int i = 0; i < 4; i++) {
        int r0 = m0 + ty * 8 + 2 * i;
        int r1 = r0 + 1;
        float an0 = 0.f, an1 = 0.f;
        if (MODE == 1) {
            an0 = (r0 < Mloc) ? anp[r0] : 0.f;
            an1 = (r1 < Mloc) ? anp[r1] : 0.f;
        }
#pragma unroll
        for (int j = 0; j < NCOL; j++) {
            int cc = n0 + tx * NCOL + j;
            if (cc >= N) continue;
            float2 v2 = upk(acc2[i][j]);
            float v0 = v2.x, v1 = v2.y;
            if (MODE == 1) {
                float bb = bnp[cc];
                v0 = sqrtf(fmaxf(an0 + bb - 2.f * v0, 0.f));
                v1 = sqrtf(fmaxf(an1 + bb - 2.f * v1, 0.f));
            }
            if (r0 < Mloc) C[(size_t)r0 * ldc + cc] = v0;
            if (r1 < Mloc) C[(size_t)r1 * ldc + cc] = v1;
        }
    }
}

// ---------------- embedding build: relu(P[f0]+Q[f1]+b) + squared norm ----------------
__global__ void k_embed(const float* __restrict__ bias) {
    int row = blockIdx.x;         // [0, NQT+NST)
    int tid = threadIdx.x;        // 256
    float *dst, *nout;
    int f0, f1;
    if (row < NQT) {
        int n = row / TT, t = row % TT;
        f0 = n * SEQ + c_p0[t];
        f1 = n * SEQ + c_p1[t];
        dst = g_QE + (size_t)row * D; nout = &g_qn[row];
    } else {
        int si = row - NQT;
        int c = si / 225, r = si % 225;
        int s = r / TT, t = r % TT;
        int base = QF + (c * SHOT + s) * SEQ;
        f0 = base + c_p0[t];
        f1 = base + c_p1[t];
        dst = g_SE + (size_t)si * D; nout = &g_sn[si];
    }
    const float4* a0 = (const float4*)(g_EF + (size_t)f0 * 2 * D);        // W0 half of f0
    const float4* a1 = (const float4*)(g_EF + (size_t)f1 * 2 * D + D);    // W1 half of f1
    const float4* bb = (const float4*)bias;
    float4* o4 = (float4*)dst;
    float nrm = 0.f;
    for (int v = tid; v < D / 4; v += 256) {
        float4 x = a0[v], y = a1[v], z = bb[v], r4;
        r4.x = fmaxf(x.x + y.x + z.x, 0.f);
        r4.y = fmaxf(x.y + y.y + z.y, 0.f);
        r4.z = fmaxf(x.z + y.z + z.z, 0.f);
        r4.w = fmaxf(x.w + y.w + z.w, 0.f);
        o4[v] = r4;
        nrm += r4.x * r4.x + r4.y * r4.y + r4.z * r4.z + r4.w * r4.w;
    }
    __shared__ float sred[256];
    sred[tid] = nrm; __syncthreads();
    for (int s = 128; s; s >>= 1) {
        if (tid < s) sred[tid] += sred[tid + s];
        __syncthreads();
    }
    if (tid == 0) *nout = sred[0];
}

// ---------------- per-(class, query-tuple) reductions: rowmax, argmax, ave ----------------
__global__ void k_classred() {
    int w = (blockIdx.x * blockDim.x + threadIdx.x) >> 5;
    int lane = threadIdx.x & 31;
    if (w >= WAY * NQT) return;
    int c = w / NQT, qi = w % NQT;
    const float* row = g_DQ + (size_t)qi * NST + c * 225;
    float best = -1.f; int bidx = 0;
    float g0 = -1.f, g1 = -1.f, g2 = -1.f, g3 = -1.f, g4 = -1.f;
    for (int j = lane; j < 225; j += 32) {
        float v = row[j];
        if (v > best) { best = v; bidx = j; }
        int s = j % 5;   // dist_class reshape: j = t'*5 + s'
        if      (s == 0) g0 = fmaxf(g0, v);
        else if (s == 1) g1 = fmaxf(g1, v);
        else if (s == 2) g2 = fmaxf(g2, v);
        else if (s == 3) g3 = fmaxf(g3, v);
        else             g4 = fmaxf(g4, v);
    }
#pragma unroll
    for (int off = 16; off; off >>= 1) {
        float ob = __shfl_down_sync(0xffffffff, best, off);
        int   oi = __shfl_down_sync(0xffffffff, bidx, off);
        if (ob > best || (ob == best && oi < bidx)) { best = ob; bidx = oi; }
        g0 = fmaxf(g0, __shfl_down_sync(0xffffffff, g0, off));
        g1 = fmaxf(g1, __shfl_down_sync(0xffffffff, g1, off));
        g2 = fmaxf(g2, __shfl_down_sync(0xffffffff, g2, off));
        g3 = fmaxf(g3, __shfl_down_sync(0xffffffff, g3, off));
        g4 = fmaxf(g4, __shfl_down_sync(0xffffffff, g4, off));
    }
    if (lane == 0) {
        g_rowmax[w] = best;
        g_pos[w]    = bidx;
        g_ave[w]    = (g0 + g1 + g2 + g3 + g4) * 0.2f;
    }
}

// ---------------- record accumulation over 3375 query tuples ----------------
__global__ void k_record() {
    int c = blockIdx.y;
    int tid = threadIdx.x;                 // 128
    __shared__ int srec[NST];
    for (int j = tid; j < NST; j += 128) srec[j] = 0;
    __syncthreads();
    int q0 = blockIdx.x * 125;             // 27 chunks * 125 = 3375
    for (int qi = q0; qi < q0 + 125; qi++) {
        int   p = g_pos[c * NQT + qi];
        float a = g_ave[c * NQT + qi];
        const float* row = g_SD + (size_t)(c * 225 + p) * NST;
        for (int j = tid; j < NST; j += 128)
            srec[j] += (row[j] > a) ? 1 : 0;
    }
    __syncthreads();
    for (int j = tid; j < NST; j += 128)
        atomicAdd(&g_record[c * NST + j], srec[j]);
}

// ---------------- threshold + mask + msum per class ----------------
__global__ void k_mask() {
    int c = blockIdx.x;
    int tid = threadIdx.x;                 // 256
    __shared__ float sred[256];
    __shared__ int   snz[256];
    __shared__ float s_thr;
    float msum_acc = 0.f;
    for (int m = 0; m < WAY; m++) {
        if (m == c) {
            if (tid < 225) g_mask[c * NST + m * 225 + tid] = 0.f;
            continue;
        }
        int rec = 0;
        if (tid < 225) rec = g_record[c * NST + m * 225 + tid];
        sred[tid] = (tid < 225) ? (float)rec : 0.f;
        snz[tid]  = (tid < 225 && rec != 0) ? 1 : 0;
        __syncthreads();
        for (int s = 128; s; s >>= 1) {
            if (tid < s) { sred[tid] += sred[tid + s]; snz[tid] += snz[tid + s]; }
            __syncthreads();
        }
        if (tid == 0) s_thr = sred[0] / fmaxf((float)snz[0], 1.f);
        __syncthreads();
        if (tid < 225) {
            float mk = ((float)rec < s_thr) ? 1.f : 0.f;
            g_mask[c * NST + m * 225 + tid] = mk;
            msum_acc += mk;
        }
        __syncthreads();
    }
    sred[tid] = msum_acc; __syncthreads();
    for (int s = 128; s; s >>= 1) {
        if (tid < s) sred[tid] += sred[tid + s];
        __syncthreads();
    }
    if (tid == 0) g_msum[c] = fmaxf(sred[0], 1.f);
}

// ---------------- masked mean over DQ columns -> contrast ----------------
__global__ void k_contrast() {
    int qi = blockIdx.x;
    int tid = threadIdx.x;                 // 128
    const float* row = g_DQ + (size_t)qi * NST;
    float a0 = 0.f, a1 = 0.f, a2 = 0.f, a3 = 0.f, a4 = 0.f;
    for (int j = tid; j < NST; j += 128) {
        float d = row[j];
        a0 += d * g_mask[0 * NST + j];
        a1 += d * g_mask[1 * NST + j];
        a2 += d * g_mask[2 * NST + j];
        a3 += d * g_mask[3 * NST + j];
        a4 += d * g_mask[4 * NST + j];
    }
    __shared__ float red[WAY][128];
    red[0][tid] = a0; red[1][tid] = a1; red[2][tid] = a2;
    red[3][tid] = a3; red[4][tid] = a4;
    __syncthreads();
    for (int s = 64; s; s >>= 1) {
        if (tid < s)
#pragma unroll
            for (int cc = 0; cc < WAY; cc++) red[cc][tid] += red[cc][tid + s];
        __syncthreads();
    }
    if (tid < WAY) {
        float val = red[tid][0] / g_msum[tid] * (1.f / (4.f * 45.f));
        atomicAdd(&g_contrast[(qi / TT) * WAY + tid], val);
    }
}

// ---------------- final outputs ----------------
__global__ void k_final(float* __restrict__ out, int out_size) {
    int idx = blockIdx.x * blockDim.x + threadIdx.x;
    if (idx >= NQ * WAY) return;
    int n = idx / WAY, c = idx % WAY;
    float s = 0.f;
    for (int t = 0; t < TT; t++) s += g_rowmax[c * NQT + n * TT + t];
    float dm = s * (1.f / 45.f);
    float ct = g_contrast[idx];
    float lg = dm / (ct + dm);
    if (idx < out_size) out[idx] = dm;
    if (NQ * WAY + idx < out_size) out[NQ * WAY + idx] = lg;
}

// ---------------- launch ----------------
extern "C" void kernel_launch(void* const* d_in, const int* in_sizes, int n_in,
                              void* d_out, int out_size) {
    const float* support = (const float*)d_in[0];   // [25,10,2048]
    const float* queries = (const float*)d_in[2];   // [75,10,2048]
    const float* W       = (const float*)d_in[3];   // [2048,4096]
    const float* bias    = (const float*)d_in[4];   // [2048]
    float* out = (float*)d_out;

    float* EF;
    cudaGetSymbolAddress((void**)&EF, g_EF);

    k_init<<<22, 256>>>();

    // Fused per-frame projection: [1000 frames, 4096 outs] = frames @ [W0;W1]^T
    // grid 32x8 = 256 CTAs -> one 2-CTA/SM wave
    sgemm_nt<2, 128, 8><<<dim3(32, 8), 256>>>(queries, support, W, EF,
                                              NF, 2 * D, 2 * D);

    k_embed<<<NQT + NST, 256>>>(bias);

    // merged distance GEMMs: y<27 -> DQ tiles, y>=27 -> SD tiles
    // grid 8x36 = 288 CTAs -> one 2-CTA/SM wave (296 slots)
    sgemm_nt<1, 144, 9><<<dim3(8, 36), 256>>>(nullptr, nullptr, nullptr, nullptr,
                                              0, NST, NST);

    k_classred<<<2110, 256>>>();
    k_record<<<dim3(27, WAY), 128>>>();
    k_mask<<<WAY, 256>>>();
    k_contrast<<<NQT, 128>>>();
    k_final<<<2, 256>>>(out, out_size);
}

// round 7
// speedup vs baseline: 3.0592x; 3.0592x over previous
#include <cuda_runtime.h>
#include <cuda_bf16.h>
#include <math.h>

// ---------------- problem constants ----------------
#define SEQ   10
#define WAY   5
#define SHOT  5
#define TT    45          // C(10,2)
#define D     2048
#define NQ    75
#define NS    25
#define NQT   3375        // NQ*TT
#define NST   1125        // NS*TT
#define QF    750         // query frames
#define NF    1000        // total frames

__constant__ int c_p0[TT] = {0,0,0,0,0,0,0,0,0, 1,1,1,1,1,1,1,1, 2,2,2,2,2,2,2,
                             3,3,3,3,3,3, 4,4,4,4,4, 5,5,5,5, 6,6,6, 7,7, 8};
__constant__ int c_p1[TT] = {1,2,3,4,5,6,7,8,9, 2,3,4,5,6,7,8,9, 3,4,5,6,7,8,9,
                             4,5,6,7,8,9, 5,6,7,8,9, 6,7,8,9, 7,8,9, 8,9, 9};

// ---------------- scratch ----------------
__device__ __nv_bfloat16 g_Fh[NF * D];       // frame hi
__device__ __nv_bfloat16 g_Fl[NF * D];       // frame lo
__device__ __nv_bfloat16 g_Wh[4096 * D];     // W rows remapped: n -> W[(n&2047)][(n&2048)+k]
__device__ __nv_bfloat16 g_Wl[4096 * D];
__device__ float g_EF[NF * 4096];            // per-frame projections fp32
__device__ __nv_bfloat16 g_QEh[NQT * D];     // q_embed hi/lo
__device__ __nv_bfloat16 g_QEl[NQT * D];
__device__ __nv_bfloat16 g_SEh[NST * D];
__device__ __nv_bfloat16 g_SEl[NST * D];
__device__ float g_qn[NQT];
__device__ float g_sn[NST];
__device__ float g_DQ[NQT * NST];
__device__ float g_SD[NST * NST];
__device__ float g_rowmax[WAY * NQT];
__device__ int   g_pos[WAY * NQT];
__device__ float g_ave[WAY * NQT];
__device__ int   g_record[WAY * NST];
__device__ float g_mask[WAY * NST];
__device__ float g_msum[WAY];
__device__ float g_contrast[NQ * WAY];

typedef unsigned long long u64;
typedef unsigned int u32;

__device__ __forceinline__ u32 smem_u32(const void* p) {
    u32 a;
    asm("{ .reg .u64 t; cvta.to.shared.u64 t, %1; cvt.u32.u64 %0, t; }" : "=r"(a) : "l"(p));
    return a;
}

// ---------------- init ----------------
__global__ void k_init() {
    int i = blockIdx.x * blockDim.x + threadIdx.x;
    if (i < WAY * NST) g_record[i] = 0;
    if (i < NQ * WAY)  g_contrast[i] = 0.f;
}

// ---------------- input hi/lo conversion ----------------
__global__ void k_cvt(const float* __restrict__ q, const float* __restrict__ s,
                      const float* __restrict__ w) {
    int i = blockIdx.x * 256 + threadIdx.x;
    const int NFR = NF * D;              // 2,048,000
    const int NWE = 4096 * D;            // 8,388,608
    if (i < NFR) {
        float x = (i < QF * D) ? q[i] : s[i - QF * D];
        __nv_bfloat16 h = __float2bfloat16(x);
        g_Fh[i] = h;
        g_Fl[i] = __float2bfloat16(x - __bfloat162float(h));
    } else if (i < NFR + NWE) {
        int j = i - NFR;
        int n = j >> 11, k = j & 2047;
        float x = w[(size_t)(n & 2047) * 4096 + (n & 2048) + k];
        __nv_bfloat16 h = __float2bfloat16(x);
        g_Wh[j] = h;
        g_Wl[j] = __float2bfloat16(x - __bfloat162float(h));
    }
}

// ---------------- mma.sync bf16 GEMM, K=6144 (hi/lo 3-term), 128x128 tiles ------
// A/B tiles in smem: 128 rows x 32 k bf16, row stride 40 elems (80B) -> conflict-free
// ldmatrix. 2-stage cp.async ring (16B ops). 8 warps, each 64(M)x32(N) via m16n8k16.
// MODE 1: distance GEMMs (y<27: DQ rows A=QE; else SD rows A=SE; B=SE),
//         epilogue sqrt(max(an+bn-2acc,0)).
// MODE 2: embedding GEMM: A=frames, B=remapped W, C=EF fp32 plain.
#define STGB 20480        // bytes per stage: A 10240 + B 10240
#define NTILE 192         // 3 segments * 64 k-tiles (BK=32)

template<int MODE>
__global__ void __launch_bounds__(256, 2) gemm_mma() {
    __shared__ __align__(16) char smem[2 * STGB];
    int tid = threadIdx.x;
    int lane = tid & 31, wid = tid >> 5;
    int wm = wid & 1, wn = wid >> 1;

    int n0 = blockIdx.x * 128;
    int m0, Mloc, Nloc, ldc;
    const __nv_bfloat16 *Ah, *Al, *Bh, *Bl;
    const float *anp = nullptr, *bnp = nullptr;
    float* C;
    if (MODE == 1) {
        int y = blockIdx.y;
        if (y < 27) { m0 = y * 128;        Ah = g_QEh; Al = g_QEl; anp = g_qn; C = g_DQ; Mloc = NQT; }
        else        { m0 = (y - 27) * 128; Ah = g_SEh; Al = g_SEl; anp = g_sn; C = g_SD; Mloc = NST; }
        Bh = g_SEh; Bl = g_SEl; bnp = g_sn; Nloc = NST; ldc = NST;
    } else {
        m0 = blockIdx.y * 128;
        Ah = g_Fh; Al = g_Fl; Bh = g_Wh; Bl = g_Wl;
        C = g_EF; Mloc = NF; Nloc = 4096; ldc = 4096;
    }

    // ---- loader slots: 2 per thread for A, 2 for B (16B chunks) ----
    const __nv_bfloat16 *aPH[2], *aPL[2], *bPH[2], *bPL[2];
    u32 aDst[2], bDst[2];
#pragma unroll
    for (int i = 0; i < 2; i++) {
        int s = tid + i * 256;            // [0,512)
        int row = s >> 2, kc = s & 3;     // kc = 16B chunk within 32-elem k
        int r = m0 + row; int rc = (r < Mloc) ? r : 0;
        aPH[i] = Ah + (size_t)rc * D + kc * 8;
        aPL[i] = Al + (size_t)rc * D + kc * 8;
        int nr = n0 + row; int nc = (nr < Nloc) ? nr : 0;
        bPH[i] = Bh + (size_t)nc * D + kc * 8;
        bPL[i] = Bl + (size_t)nc * D + kc * 8;
        aDst[i] = smem_u32(smem + row * 80 + kc * 16);
        bDst[i] = smem_u32(smem + 10240 + row * 80 + kc * 16);
    }

    // ---- ldmatrix source addresses (stage 0) ----
    u32 aLd[4], bLd[2];
#pragma unroll
    for (int mi = 0; mi < 4; mi++) {
        int rrow = wm * 64 + mi * 16 + (lane & 15);
        int rcol = (lane >> 4) * 8;       // elements
        aLd[mi] = smem_u32(smem + rrow * 80 + rcol * 2);
    }
#pragma unroll
    for (int nb = 0; nb < 2; nb++) {
        int brow = wn * 32 + nb * 16 + (lane & 7) + ((lane >> 4) & 1) * 8;
        int bcol = ((lane >> 3) & 1) * 8; // elements
        bLd[nb] = smem_u32(smem + 10240 + brow * 80 + bcol * 2);
    }

    float acc[4][4][4];
#pragma unroll
    for (int mi = 0; mi < 4; mi++)
#pragma unroll
        for (int ni = 0; ni < 4; ni++)
#pragma unroll
            for (int x = 0; x < 4; x++) acc[mi][ni][x] = 0.f;

    auto issue = [&](int t) {
        int seg = t >> 6;
        int kk = (t & 63) * 32;
        u32 so = (u32)(t & 1) * STGB;
#pragma unroll
        for (int i = 0; i < 2; i++) {
            const __nv_bfloat16* ga = (seg < 2 ? aPH[i] : aPL[i]) + kk;   // A: hi,hi,lo
            const __nv_bfloat16* gb = (seg == 1 ? bPL[i] : bPH[i]) + kk;  // B: hi,lo,hi
            asm volatile("cp.async.cg.shared.global [%0], [%1], 16;" :: "r"(aDst[i] + so), "l"(ga));
            asm volatile("cp.async.cg.shared.global [%0], [%1], 16;" :: "r"(bDst[i] + so), "l"(gb));
        }
        asm volatile("cp.async.commit_group;");
    };

    issue(0);
    issue(1);

    for (int t = 0; t < NTILE; t++) {
        if (t + 1 < NTILE) asm volatile("cp.async.wait_group 1;");
        else               asm volatile("cp.async.wait_group 0;");
        __syncthreads();
        u32 so = (u32)(t & 1) * STGB;
#pragma unroll
        for (int ki = 0; ki < 2; ki++) {
            u32 af[4][4], bf_[2][4];
#pragma unroll
            for (int mi = 0; mi < 4; mi++)
                asm volatile("ldmatrix.sync.aligned.m8n8.x4.shared.b16 {%0,%1,%2,%3}, [%4];"
                    : "=r"(af[mi][0]), "=r"(af[mi][1]), "=r"(af[mi][2]), "=r"(af[mi][3])
                    : "r"(aLd[mi] + so + ki * 32));
#pragma unroll
            for (int nb = 0; nb < 2; nb++)
                asm volatile("ldmatrix.sync.aligned.m8n8.x4.shared.b16 {%0,%1,%2,%3}, [%4];"
                    : "=r"(bf_[nb][0]), "=r"(bf_[nb][1]), "=r"(bf_[nb][2]), "=r"(bf_[nb][3])
                    : "r"(bLd[nb] + so + ki * 32));
#pragma unroll
            for (int mi = 0; mi < 4; mi++)
#pragma unroll
                for (int ni = 0; ni < 4; ni++) {
                    u32 b0 = bf_[ni >> 1][(ni & 1) * 2];
                    u32 b1 = bf_[ni >> 1][(ni & 1) * 2 + 1];
                    asm volatile(
                        "mma.sync.aligned.m16n8k16.row.col.f32.bf16.bf16.f32 "
                        "{%0,%1,%2,%3}, {%4,%5,%6,%7}, {%8,%9}, {%0,%1,%2,%3};"
                        : "+f"(acc[mi][ni][0]), "+f"(acc[mi][ni][1]),
                          "+f"(acc[mi][ni][2]), "+f"(acc[mi][ni][3])
                        : "r"(af[mi][0]), "r"(af[mi][1]), "r"(af[mi][2]), "r"(af[mi][3]),
                          "r"(b0), "r"(b1));
                }
        }
        __syncthreads();
        if (t + 2 < NTILE) issue(t + 2);
    }

    // ---- epilogue ----
#pragma unroll
    for (int mi = 0; mi < 4; mi++) {
        int r0 = m0 + wm * 64 + mi * 16 + (lane >> 2);
        int r1 = r0 + 8;
        float an0 = 0.f, an1 = 0.f;
        if (MODE == 1) {
            an0 = (r0 < Mloc) ? anp[r0] : 0.f;
            an1 = (r1 < Mloc) ? anp[r1] : 0.f;
        }
#pragma unroll
        for (int ni = 0; ni < 4; ni++) {
            int c0 = n0 + wn * 32 + ni * 8 + (lane & 3) * 2;
            float v0 = acc[mi][ni][0], v1 = acc[mi][ni][1];
            float v2 = acc[mi][ni][2], v3 = acc[mi][ni][3];
            if (MODE == 1) {
                float b0 = (c0 < Nloc) ? bnp[c0] : 0.f;
                float b1 = (c0 + 1 < Nloc) ? bnp[c0 + 1] : 0.f;
                v0 = sqrtf(fmaxf(an0 + b0 - 2.f * v0, 0.f));
                v1 = sqrtf(fmaxf(an0 + b1 - 2.f * v1, 0.f));
                v2 = sqrtf(fmaxf(an1 + b0 - 2.f * v2, 0.f));
                v3 = sqrtf(fmaxf(an1 + b1 - 2.f * v3, 0.f));
            }
            if (r0 < Mloc) {
                if (c0 < Nloc)     C[(size_t)r0 * ldc + c0]     = v0;
                if (c0 + 1 < Nloc) C[(size_t)r0 * ldc + c0 + 1] = v1;
            }
            if (r1 < Mloc) {
                if (c0 < Nloc)     C[(size_t)r1 * ldc + c0]     = v2;
                if (c0 + 1 < Nloc) C[(size_t)r1 * ldc + c0 + 1] = v3;
            }
        }
    }
}

// ---------------- embedding build: relu(P[f0]+Q[f1]+b) -> hi/lo bf16 + norm ------
__global__ void k_embed(const float* __restrict__ bias) {
    int row = blockIdx.x;         // [0, NQT+NST)
    int tid = threadIdx.x;        // 256
    __nv_bfloat16 *dh, *dl;
    float* nout;
    int f0, f1;
    if (row < NQT) {
        int n = row / TT, t = row % TT;
        f0 = n * SEQ + c_p0[t];
        f1 = n * SEQ + c_p1[t];
        dh = g_QEh + (size_t)row * D; dl = g_QEl + (size_t)row * D; nout = &g_qn[row];
    } else {
        int si = row - NQT;
        int c = si / 225, rr = si % 225;
        int s = rr / TT, t = rr % TT;
        int base = QF + (c * SHOT + s) * SEQ;
        f0 = base + c_p0[t];
        f1 = base + c_p1[t];
        dh = g_SEh + (size_t)si * D; dl = g_SEl + (size_t)si * D; nout = &g_sn[si];
    }
    const float4* a0 = (const float4*)(g_EF + (size_t)f0 * 4096);          // P half
    const float4* a1 = (const float4*)(g_EF + (size_t)f1 * 4096 + D);      // Q half
    const float4* bb = (const float4*)bias;
    float nrm = 0.f;
    for (int v = tid; v < D / 4; v += 256) {
        float4 x = a0[v], y = a1[v], z = bb[v];
        float r0 = fmaxf(x.x + y.x + z.x, 0.f);
        float r1 = fmaxf(x.y + y.y + z.y, 0.f);
        float r2 = fmaxf(x.z + y.z + z.z, 0.f);
        float r3 = fmaxf(x.w + y.w + z.w, 0.f);
        nrm += r0 * r0 + r1 * r1 + r2 * r2 + r3 * r3;
        __nv_bfloat16 h0 = __float2bfloat16(r0), h1 = __float2bfloat16(r1);
        __nv_bfloat16 h2 = __float2bfloat16(r2), h3 = __float2bfloat16(r3);
        ((__nv_bfloat162*)dh)[v * 2]     = __nv_bfloat162(h0, h1);
        ((__nv_bfloat162*)dh)[v * 2 + 1] = __nv_bfloat162(h2, h3);
        ((__nv_bfloat162*)dl)[v * 2]     = __nv_bfloat162(
            __float2bfloat16(r0 - __bfloat162float(h0)),
            __float2bfloat16(r1 - __bfloat162float(h1)));
        ((__nv_bfloat162*)dl)[v * 2 + 1] = __nv_bfloat162(
            __float2bfloat16(r2 - __bfloat162float(h2)),
            __float2bfloat16(r3 - __bfloat162float(h3)));
    }
    __shared__ float sred[256];
    sred[tid] = nrm; __syncthreads();
    for (int s = 128; s; s >>= 1) {
        if (tid < s) sred[tid] += sred[tid + s];
        __syncthreads();
    }
    if (tid == 0) *nout = sred[0];
}

// ---------------- per-(class, query-tuple) reductions ----------------
__global__ void k_classred() {
    int w = (blockIdx.x * blockDim.x + threadIdx.x) >> 5;
    int lane = threadIdx.x & 31;
    if (w >= WAY * NQT) return;
    int c = w / NQT, qi = w % NQT;
    const float* row = g_DQ + (size_t)qi * NST + c * 225;
    float best = -1.f; int bidx = 0;
    float g0 = -1.f, g1 = -1.f, g2 = -1.f, g3 = -1.f, g4 = -1.f;
    for (int j = lane; j < 225; j += 32) {
        float v = row[j];
        if (v > best) { best = v; bidx = j; }
        int s = j % 5;
        if      (s == 0) g0 = fmaxf(g0, v);
        else if (s == 1) g1 = fmaxf(g1, v);
        else if (s == 2) g2 = fmaxf(g2, v);
        else if (s == 3) g3 = fmaxf(g3, v);
        else             g4 = fmaxf(g4, v);
    }
#pragma unroll
    for (int off = 16; off; off >>= 1) {
        float ob = __shfl_down_sync(0xffffffff, best, off);
        int   oi = __shfl_down_sync(0xffffffff, bidx, off);
        if (ob > best || (ob == best && oi < bidx)) { best = ob; bidx = oi; }
        g0 = fmaxf(g0, __shfl_down_sync(0xffffffff, g0, off));
        g1 = fmaxf(g1, __shfl_down_sync(0xffffffff, g1, off));
        g2 = fmaxf(g2, __shfl_down_sync(0xffffffff, g2, off));
        g3 = fmaxf(g3, __shfl_down_sync(0xffffffff, g3, off));
        g4 = fmaxf(g4, __shfl_down_sync(0xffffffff, g4, off));
    }
    if (lane == 0) {
        g_rowmax[w] = best;
        g_pos[w]    = bidx;
        g_ave[w]    = (g0 + g1 + g2 + g3 + g4) * 0.2f;
    }
}

// ---------------- record accumulation ----------------
__global__ void k_record() {
    int c = blockIdx.y;
    int tid = threadIdx.x;                 // 128
    __shared__ int srec[NST];
    for (int j = tid; j < NST; j += 128) srec[j] = 0;
    __syncthreads();
    int q0 = blockIdx.x * 125;
    for (int qi = q0; qi < q0 + 125; qi++) {
        int   p = g_pos[c * NQT + qi];
        float a = g_ave[c * NQT + qi];
        const float* row = g_SD + (size_t)(c * 225 + p) * NST;
        for (int j = tid; j < NST; j += 128)
            srec[j] += (row[j] > a) ? 1 : 0;
    }
    __syncthreads();
    for (int j = tid; j < NST; j += 128)
        atomicAdd(&g_record[c * NST + j], srec[j]);
}

// ---------------- threshold + mask + msum ----------------
__global__ void k_mask() {
    int c = blockIdx.x;
    int tid = threadIdx.x;                 // 256
    __shared__ float sred[256];
    __shared__ int   snz[256];
    __shared__ float s_thr;
    float msum_acc = 0.f;
    for (int m = 0; m < WAY; m++) {
        if (m == c) {
            if (tid < 225) g_mask[c * NST + m * 225 + tid] = 0.f;
            continue;
        }
        int rec = 0;
        if (tid < 225) rec = g_record[c * NST + m * 225 + tid];
        sred[tid] = (tid < 225) ? (float)rec : 0.f;
        snz[tid]  = (tid < 225 && rec != 0) ? 1 : 0;
        __syncthreads();
        for (int s = 128; s; s >>= 1) {
            if (tid < s) { sred[tid] += sred[tid + s]; snz[tid] += snz[tid + s]; }
            __syncthreads();
        }
        if (tid == 0) s_thr = sred[0] / fmaxf((float)snz[0], 1.f);
        __syncthreads();
        if (tid < 225) {
            float mk = ((float)rec < s_thr) ? 1.f : 0.f;
            g_mask[c * NST + m * 225 + tid] = mk;
            msum_acc += mk;
        }
        __syncthreads();
    }
    sred[tid] = msum_acc; __syncthreads();
    for (int s = 128; s; s >>= 1) {
        if (tid < s) sred[tid] += sred[tid + s];
        __syncthreads();
    }
    if (tid == 0) g_msum[c] = fmaxf(sred[0], 1.f);
}

// ---------------- masked mean -> contrast ----------------
__global__ void k_contrast() {
    int qi = blockIdx.x;
    int tid = threadIdx.x;                 // 128
    const float* row = g_DQ + (size_t)qi * NST;
    float a0 = 0.f, a1 = 0.f, a2 = 0.f, a3 = 0.f, a4 = 0.f;
    for (int j = tid; j < NST; j += 128) {
        float d = row[j];
        a0 += d * g_mask[0 * NST + j];
        a1 += d * g_mask[1 * NST + j];
        a2 += d * g_mask[2 * NST + j];
        a3 += d * g_mask[3 * NST + j];
        a4 += d * g_mask[4 * NST + j];
    }
    __shared__ float red[WAY][128];
    red[0][tid] = a0; red[1][tid] = a1; red[2][tid] = a2;
    red[3][tid] = a3; red[4][tid] = a4;
    __syncthreads();
    for (int s = 64; s; s >>= 1) {
        if (tid < s)
#pragma unroll
            for (int cc = 0; cc < WAY; cc++) red[cc][tid] += red[cc][tid + s];
        __syncthreads();
    }
    if (tid < WAY) {
        float val = red[tid][0] / g_msum[tid] * (1.f / (4.f * 45.f));
        atomicAdd(&g_contrast[(qi / TT) * WAY + tid], val);
    }
}

// ---------------- final outputs ----------------
__global__ void k_final(float* __restrict__ out, int out_size) {
    int idx = blockIdx.x * blockDim.x + threadIdx.x;
    if (idx >= NQ * WAY) return;
    int n = idx / WAY, c = idx % WAY;
    float s = 0.f;
    for (int t = 0; t < TT; t++) s += g_rowmax[c * NQT + n * TT + t];
    float dm = s * (1.f / 45.f);
    float ct = g_contrast[idx];
    float lg = dm / (ct + dm);
    if (idx < out_size) out[idx] = dm;
    if (NQ * WAY + idx < out_size) out[NQ * WAY + idx] = lg;
}

// ---------------- launch ----------------
extern "C" void kernel_launch(void* const* d_in, const int* in_sizes, int n_in,
                              void* d_out, int out_size) {
    const float* support = (const float*)d_in[0];   // [25,10,2048]
    const float* queries = (const float*)d_in[2];   // [75,10,2048]
    const float* W       = (const float*)d_in[3];   // [2048,4096]
    const float* bias    = (const float*)d_in[4];   // [2048]
    float* out = (float*)d_out;

    k_init<<<22, 256>>>();

    // hi/lo conversion of frames + remapped W
    k_cvt<<<(NF * D + 4096 * D + 255) / 256, 256>>>(queries, support, W);

    // embedding GEMM: EF[1000, 4096] = frames @ Wmap^T   (mma.sync bf16, K=6144)
    gemm_mma<2><<<dim3(32, 8), 256>>>();

    k_embed<<<NQT + NST, 256>>>(bias);

    // distance GEMMs: y<27 DQ, y>=27 SD   (mma.sync bf16, K=6144)
    gemm_mma<1><<<dim3(9, 36), 256>>>();

    k_classred<<<2110, 256>>>();
    k_record<<<dim3(27, WAY), 128>>>();
    k_mask<<<WAY, 256>>>();
    k_contrast<<<NQT, 128>>>();
    k_final<<<2, 256>>>(out, out_size);
}